// round 16
// baseline (speedup 1.0000x reference)
#include <cuda_runtime.h>
#include <cuda_bf16.h>
#include <cstdint>
#include <math.h>

#define NMAX 50000
#define EMAX 800000

// ================= scratch (device globals) =================
__device__ __align__(16) float g_h1[(size_t)NMAX * 256];
__device__ __align__(16) float g_h2[(size_t)NMAX * 256];
__device__ __align__(16) float g_as1[NMAX * 2];
__device__ __align__(16) float g_ad1[NMAX * 2];
__device__ __align__(16) float g_as2[NMAX];
__device__ __align__(16) float g_ad2[NMAX];
// CSR by destination
__device__ int g_deg[NMAX];
__device__ int g_off[NMAX + 1];
__device__ int g_cur[NMAX];
__device__ int g_csr[EMAX];
__device__ int g_blksum[64];
// split-bf16 operands
__device__ __align__(16) __nv_bfloat16 g_ahi[(size_t)NMAX * 256];
__device__ __align__(16) __nv_bfloat16 g_alo[(size_t)NMAX * 256];
__device__ __align__(16) __nv_bfloat16 g_bhi[256 * 256];      // W1
__device__ __align__(16) __nv_bfloat16 g_blo[256 * 256];
__device__ __align__(16) __nv_bfloat16 g_w2hi[256 * 256];     // W2
__device__ __align__(16) __nv_bfloat16 g_w2lo[256 * 256];
__device__ __align__(16) __nv_bfloat16 g_ghi[(size_t)1024 * 256];  // G^T
__device__ __align__(16) __nv_bfloat16 g_glo[(size_t)1024 * 256];

__device__ __forceinline__ uint32_t smem_u32(const void* p) {
    uint32_t a;
    asm("{ .reg .u64 t; cvta.to.shared.u64 t, %1; cvt.u32.u64 %0, t; }" : "=r"(a) : "l"(p));
    return a;
}

// ================= split store helper =================
__device__ __forceinline__ void split_store4(__nv_bfloat16* hip, __nv_bfloat16* lop, float4 v) {
    __nv_bfloat16 h0 = __float2bfloat16(v.x), h1 = __float2bfloat16(v.y);
    __nv_bfloat16 h2 = __float2bfloat16(v.z), h3 = __float2bfloat16(v.w);
    __nv_bfloat16 l0 = __float2bfloat16(v.x - __bfloat162float(h0));
    __nv_bfloat16 l1 = __float2bfloat16(v.y - __bfloat162float(h1));
    __nv_bfloat16 l2 = __float2bfloat16(v.z - __bfloat162float(h2));
    __nv_bfloat16 l3 = __float2bfloat16(v.w - __bfloat162float(h3));
    uint2 uh = make_uint2(((uint32_t)__bfloat16_as_ushort(h1) << 16) | __bfloat16_as_ushort(h0),
                          ((uint32_t)__bfloat16_as_ushort(h3) << 16) | __bfloat16_as_ushort(h2));
    uint2 ul = make_uint2(((uint32_t)__bfloat16_as_ushort(l1) << 16) | __bfloat16_as_ushort(l0),
                          ((uint32_t)__bfloat16_as_ushort(l3) << 16) | __bfloat16_as_ushort(l2));
    *(uint2*)hip = uh;
    *(uint2*)lop = ul;
}

// ================= CSR build (hierarchical scan) =================
__global__ void zero_init(int N) {
    int i = blockIdx.x * blockDim.x + threadIdx.x;
    if (i < N) {
        g_deg[i] = 0;
        g_as2[i] = 0.f;
        g_ad2[i] = 0.f;
    }
}
__global__ void hist_kernel(const int* __restrict__ dst, int E) {
    int e = blockIdx.x * blockDim.x + threadIdx.x;
    if (e < E) atomicAdd(&g_deg[dst[e]], 1);
}
__global__ void scan_blk(int N) {
    __shared__ int sh[1024];
    int b = blockIdx.x, tid = threadIdx.x;
    int i = b * 1024 + tid;
    int v = (i < N) ? g_deg[i] : 0;
    sh[tid] = v;
    __syncthreads();
    for (int o = 1; o < 1024; o <<= 1) {
        int t = (tid >= o) ? sh[tid - o] : 0;
        __syncthreads();
        sh[tid] += t;
        __syncthreads();
    }
    if (i < N) g_off[i] = sh[tid] - v;
    if (tid == 1023) g_blksum[b] = sh[1023];
}
__global__ void scan_top(int nb) {
    __shared__ int sh[64];
    int tid = threadIdx.x;
    int v = (tid < nb) ? g_blksum[tid] : 0;
    sh[tid] = v;
    __syncthreads();
    for (int o = 1; o < 64; o <<= 1) {
        int t = (tid >= o) ? sh[tid - o] : 0;
        __syncthreads();
        sh[tid] += t;
        __syncthreads();
    }
    if (tid < nb) g_blksum[tid] = sh[tid] - v;
}
__global__ void scan_add(int N, int E) {
    int i = blockIdx.x * blockDim.x + threadIdx.x;
    if (i < N) {
        int o = g_off[i] + g_blksum[i >> 10];
        g_off[i] = o;
        g_cur[i] = o;
    }
    if (i == 0) g_off[N] = E;
}
__global__ void scatter_kernel(const int* __restrict__ src, const int* __restrict__ dst, int E) {
    int e = blockIdx.x * blockDim.x + threadIdx.x;
    if (e >= E) return;
    int pos = atomicAdd(&g_cur[dst[e]], 1);
    g_csr[pos] = src[e];
}

// ================= split-bf16 conversions =================
__global__ void split_x4(const float4* __restrict__ x4, size_t n4) {
    size_t i = (size_t)blockIdx.x * blockDim.x + threadIdx.x;
    if (i >= n4) return;
    float4 v = __ldg(&x4[i]);
    split_store4(g_ahi + i * 4, g_alo + i * 4, v);
}
__global__ void split_w(const float* __restrict__ W, int sel, size_t n) {
    size_t i = (size_t)blockIdx.x * blockDim.x + threadIdx.x;
    if (i >= n) return;
    float v = W[i];
    __nv_bfloat16 h = __float2bfloat16(v);
    __nv_bfloat16 l = __float2bfloat16(v - __bfloat162float(h));
    if (sel == 0) { g_bhi[i] = h;  g_blo[i] = l; }
    else          { g_w2hi[i] = h; g_w2lo[i] = l; }
}
__global__ void tsplit_g(const float* __restrict__ G) {
    __shared__ float t[32][33];
    int bx = blockIdx.x, by = blockIdx.y;
    int x = threadIdx.x, y = threadIdx.y;   // 32 x 8
#pragma unroll
    for (int i = 0; i < 4; i++)
        t[y + i * 8][x] = G[(size_t)(by * 32 + y + i * 8) * 1024 + bx * 32 + x];
    __syncthreads();
#pragma unroll
    for (int i = 0; i < 4; i++) {
        float v = t[x][y + i * 8];
        size_t idx = (size_t)(bx * 32 + y + i * 8) * 256 + by * 32 + x;
        __nv_bfloat16 h = __float2bfloat16(v);
        g_ghi[idx] = h;
        g_glo[idx] = __float2bfloat16(v - __bfloat162float(h));
    }
}

// ================= HMMA (mma.sync) GEMM =================
#define TILE_B   10240          // 128 rows * 80B (32 bf16 + 8 pad)
#define STAGE_B  (4 * TILE_B)
#define SMEM_B   (2 * STAGE_B)  // 81920 B

__device__ __forceinline__ void ldsm_x4(uint32_t* r, uint32_t addr) {
    asm volatile("ldmatrix.sync.aligned.m8n8.x4.shared.b16 {%0,%1,%2,%3}, [%4];"
        : "=r"(r[0]), "=r"(r[1]), "=r"(r[2]), "=r"(r[3]) : "r"(addr));
}
__device__ __forceinline__ void mma_bf16(float* c, const uint32_t* a, const uint32_t* b) {
    asm volatile("mma.sync.aligned.m16n8k16.row.col.f32.bf16.bf16.f32 "
        "{%0,%1,%2,%3}, {%4,%5,%6,%7}, {%8,%9}, {%0,%1,%2,%3};"
        : "+f"(c[0]), "+f"(c[1]), "+f"(c[2]), "+f"(c[3])
        : "r"(a[0]), "r"(a[1]), "r"(a[2]), "r"(a[3]), "r"(b[0]), "r"(b[1]));
}
__device__ __forceinline__ void cp16(uint32_t saddr, const void* gaddr, int szbytes) {
    asm volatile("cp.async.cg.shared.global [%0], [%1], 16, %2;"
        :: "r"(saddr), "l"(gaddr), "r"(szbytes));
}
__device__ __forceinline__ void load_tile(char* st, const __nv_bfloat16* gsrc,
                                          int grow_base, int grow_limit, int k0, int tid)
{
#pragma unroll
    for (int j = 0; j < 2; j++) {
        int idx = tid * 2 + j;
        int row = idx >> 2, kc = idx & 3;
        int grow = grow_base + row;
        int ok = (grow < grow_limit);
        const __nv_bfloat16* gp = gsrc + (size_t)(ok ? grow : 0) * 256 + k0 + kc * 8;
        uint32_t sa = smem_u32(st + row * 80 + kc * 16);
        cp16(sa, gp, ok ? 16 : 0);
    }
}

__global__ __launch_bounds__(256, 2) void gemm_hmma(
    int Nrows, int row0, int mode,
    const float* __restrict__ av_s, const float* __restrict__ av_d,
    const float* __restrict__ mu, float* __restrict__ outp)
{
    extern __shared__ char smem[];
    int tid = threadIdx.x;
    int wid = tid >> 5;
    int lane = tid & 31;
    int warp_m = wid & 3;
    int warp_n = wid >> 2;
    int bm = row0 + blockIdx.x * 128;
    int bn = blockIdx.y * 128;

    const __nv_bfloat16* Bhi = (mode == 0) ? g_bhi : (mode == 1 ? g_w2hi : g_ghi);
    const __nv_bfloat16* Blo = (mode == 0) ? g_blo : (mode == 1 ? g_w2lo : g_glo);

    float acc[2][8][4];
#pragma unroll
    for (int mt = 0; mt < 2; mt++)
#pragma unroll
        for (int nt = 0; nt < 8; nt++)
#pragma unroll
            for (int j = 0; j < 4; j++) acc[mt][nt][j] = 0.f;

    {
        char* s0 = smem;
        load_tile(s0,              g_ahi, bm, Nrows, 0, tid);
        load_tile(s0 + TILE_B,     g_alo, bm, Nrows, 0, tid);
        load_tile(s0 + 2 * TILE_B, Bhi, bn, 1 << 30, 0, tid);
        load_tile(s0 + 3 * TILE_B, Blo, bn, 1 << 30, 0, tid);
        asm volatile("cp.async.commit_group;" ::: "memory");
    }

    for (int c = 0; c < 8; c++) {
        if (c < 7) {
            char* sn = smem + ((c + 1) & 1) * STAGE_B;
            int k0 = (c + 1) * 32;
            load_tile(sn,              g_ahi, bm, Nrows, k0, tid);
            load_tile(sn + TILE_B,     g_alo, bm, Nrows, k0, tid);
            load_tile(sn + 2 * TILE_B, Bhi, bn, 1 << 30, k0, tid);
            load_tile(sn + 3 * TILE_B, Blo, bn, 1 << 30, k0, tid);
            asm volatile("cp.async.commit_group;" ::: "memory");
            asm volatile("cp.async.wait_group 1;" ::: "memory");
        } else {
            asm volatile("cp.async.wait_group 0;" ::: "memory");
        }
        __syncthreads();

        char* sa_hi = smem + (c & 1) * STAGE_B;
        char* sa_lo = sa_hi + TILE_B;
        char* sb_hi = sa_hi + 2 * TILE_B;
        char* sb_lo = sa_hi + 3 * TILE_B;

#pragma unroll
        for (int ks = 0; ks < 2; ks++) {
            uint32_t ah[2][4], al[2][4];
#pragma unroll
            for (int mt = 0; mt < 2; mt++) {
                int row = warp_m * 32 + mt * 16 + (lane & 7) + ((lane >> 3) & 1) * 8;
                int kc = ks * 2 + (lane >> 4);
                uint32_t off = (uint32_t)(row * 80 + kc * 16);
                ldsm_x4(ah[mt], smem_u32(sa_hi + off));
                ldsm_x4(al[mt], smem_u32(sa_lo + off));
            }
            int g = lane >> 3;
#pragma unroll
            for (int np = 0; np < 4; np++) {
                int n0 = np * 2, n1 = np * 2 + 1;
                int brow = warp_n * 64 + (n0 + (g >> 1)) * 8 + (lane & 7);
                int bkc = ks * 2 + (g & 1);
                uint32_t boff = (uint32_t)(brow * 80 + bkc * 16);
                uint32_t bh[4], bl[4];
                ldsm_x4(bh, smem_u32(sb_hi + boff));
                ldsm_x4(bl, smem_u32(sb_lo + boff));
                mma_bf16(acc[0][n0], ah[0], bh);
                mma_bf16(acc[1][n0], ah[1], bh);
                mma_bf16(acc[0][n1], ah[0], bh + 2);
                mma_bf16(acc[1][n1], ah[1], bh + 2);
                mma_bf16(acc[0][n0], ah[0], bl);
                mma_bf16(acc[1][n0], ah[1], bl);
                mma_bf16(acc[0][n1], ah[0], bl + 2);
                mma_bf16(acc[1][n1], ah[1], bl + 2);
                mma_bf16(acc[0][n0], al[0], bh);
                mma_bf16(acc[1][n0], al[1], bh);
                mma_bf16(acc[0][n1], al[0], bh + 2);
                mma_bf16(acc[1][n1], al[1], bh + 2);
            }
        }
        __syncthreads();
    }

    // ================= epilogue =================
    if (mode < 2) {
        float* C = (mode == 0) ? g_h1 : g_h2;
#pragma unroll
        for (int mt = 0; mt < 2; mt++) {
            int r0 = bm + warp_m * 32 + mt * 16 + (lane >> 2);
#pragma unroll
            for (int nt = 0; nt < 8; nt++) {
                int gcol = bn + warp_n * 64 + nt * 8 + (lane & 3) * 2;
                if (r0 < Nrows)
                    *(float2*)(C + (size_t)r0 * 256 + gcol) =
                        make_float2(acc[mt][nt][0], acc[mt][nt][1]);
                if (r0 + 8 < Nrows)
                    *(float2*)(C + (size_t)(r0 + 8) * 256 + gcol) =
                        make_float2(acc[mt][nt][2], acc[mt][nt][3]);
            }
        }
        const float* asv = av_s + bn;
        const float* adv = av_d + bn;
        float psrc[2][2] = {{0.f, 0.f}, {0.f, 0.f}};
        float pdst[2][2] = {{0.f, 0.f}, {0.f, 0.f}};
#pragma unroll
        for (int nt = 0; nt < 8; nt++) {
            int col = warp_n * 64 + nt * 8 + (lane & 3) * 2;
            float s0 = __ldg(&asv[col]), s1 = __ldg(&asv[col + 1]);
            float d0 = __ldg(&adv[col]), d1 = __ldg(&adv[col + 1]);
#pragma unroll
            for (int mt = 0; mt < 2; mt++) {
                psrc[mt][0] += acc[mt][nt][0] * s0 + acc[mt][nt][1] * s1;
                psrc[mt][1] += acc[mt][nt][2] * s0 + acc[mt][nt][3] * s1;
                pdst[mt][0] += acc[mt][nt][0] * d0 + acc[mt][nt][1] * d1;
                pdst[mt][1] += acc[mt][nt][2] * d0 + acc[mt][nt][3] * d1;
            }
        }
#pragma unroll
        for (int o = 1; o <= 2; o <<= 1) {
#pragma unroll
            for (int mt = 0; mt < 2; mt++)
#pragma unroll
                for (int h = 0; h < 2; h++) {
                    psrc[mt][h] += __shfl_xor_sync(0xffffffffu, psrc[mt][h], o);
                    pdst[mt][h] += __shfl_xor_sync(0xffffffffu, pdst[mt][h], o);
                }
        }
        float* sred = (float*)smem;
        if ((lane & 3) == 0) {
#pragma unroll
            for (int mt = 0; mt < 2; mt++)
#pragma unroll
                for (int h = 0; h < 2; h++) {
                    int rl = warp_m * 32 + mt * 16 + h * 8 + (lane >> 2);
                    sred[warp_n * 256 + rl] = psrc[mt][h];
                    sred[warp_n * 256 + 128 + rl] = pdst[mt][h];
                }
        }
        __syncthreads();
        if (tid < 128 && bm + tid < Nrows) {
            float vs = sred[tid] + sred[256 + tid];
            float vd = sred[128 + tid] + sred[384 + tid];
            int row = bm + tid;
            if (mode == 0) {
                g_as1[row * 2 + blockIdx.y] = vs;
                g_ad1[row * 2 + blockIdx.y] = vd;
            } else {
                atomicAdd(&g_as2[row], vs);
                atomicAdd(&g_ad2[row], vd);
            }
        }
    } else {
        int kb = blockIdx.y;
        const float* muk = mu + kb * 128;
        float pn[2][2], psq[2][2];
#pragma unroll
        for (int mt = 0; mt < 2; mt++)
#pragma unroll
            for (int h = 0; h < 2; h++) { pn[mt][h] = 0.f; psq[mt][h] = 0.f; }
#pragma unroll
        for (int nt = 0; nt < 8; nt++) {
            int col = warp_n * 64 + nt * 8 + (lane & 3) * 2;
            float m0 = __ldg(&muk[col]), m1 = __ldg(&muk[col + 1]);
#pragma unroll
            for (int mt = 0; mt < 2; mt++) {
                float c0 = acc[mt][nt][0], c1 = acc[mt][nt][1];
                float c2 = acc[mt][nt][2], c3 = acc[mt][nt][3];
                pn[mt][0] += c0 * m0 + c1 * m1;  psq[mt][0] += c0 * c0 + c1 * c1;
                pn[mt][1] += c2 * m0 + c3 * m1;  psq[mt][1] += c2 * c2 + c3 * c3;
            }
        }
#pragma unroll
        for (int o = 1; o <= 2; o <<= 1) {
#pragma unroll
            for (int mt = 0; mt < 2; mt++)
#pragma unroll
                for (int h = 0; h < 2; h++) {
                    pn[mt][h]  += __shfl_xor_sync(0xffffffffu, pn[mt][h], o);
                    psq[mt][h] += __shfl_xor_sync(0xffffffffu, psq[mt][h], o);
                }
        }
        float2* sred = (float2*)smem;
        if ((lane & 3) == 0) {
#pragma unroll
            for (int mt = 0; mt < 2; mt++)
#pragma unroll
                for (int h = 0; h < 2; h++) {
                    int rl = warp_m * 32 + mt * 16 + h * 8 + (lane >> 2);
                    sred[warp_n * 128 + rl] = make_float2(pn[mt][h], psq[mt][h]);
                }
        }
        __syncthreads();
        if (tid < 128) {
            float2 p0 = sred[tid], p1 = sred[128 + tid];
            float num = p0.x + p1.x;
            float sq  = p0.y + p1.y;
            float musq = 0.f;
#pragma unroll 16
            for (int j = 0; j < 128; j++) {
                float mv = __ldg(&muk[j]);
                musq += mv * mv;
            }
            int m = bm + tid;
            if (m < Nrows)
                outp[(size_t)m * 8 + kb] = num / fmaxf(sqrtf(sq) * sqrtf(musq), 1e-8f);
        }
    }
}

// ================= CSR gather layer 1: 2 warps per node (warp = head) =================
__global__ __launch_bounds__(256) void gather_l1(const float* __restrict__ b1, int n0, int nCount) {
    int idx = blockIdx.x * blockDim.x + threadIdx.x;
    int nrel = idx >> 6;
    if (nrel >= nCount) return;
    int n = n0 + nrel;
    int h = (idx >> 5) & 1;
    int lane = idx & 31;
    float ad = __ldg(&g_ad1[2 * n + h]);
    int beg = g_off[n], end = g_off[n + 1];
    float4 acc = make_float4(0.f, 0.f, 0.f, 0.f);
    float sum = 0.f;
    const float* hb = g_h1 + h * 128;
#pragma unroll 2
    for (int j = beg; j < end; j++) {
        int s = __ldg(&g_csr[j]);
        float e = __ldg(&g_as1[2 * s + h]) + ad;
        e = e > 0.f ? e : 0.2f * e;
        float p = __expf(e);
        sum += p;
        float4 v = __ldg((const float4*)(hb + (size_t)s * 256) + lane);
        acc.x += p * v.x; acc.y += p * v.y; acc.z += p * v.z; acc.w += p * v.w;
    }
    {   // self loop
        float e = __ldg(&g_as1[2 * n + h]) + ad;
        e = e > 0.f ? e : 0.2f * e;
        float p = __expf(e);
        sum += p;
        float4 v = __ldg((const float4*)(hb + (size_t)n * 256) + lane);
        acc.x += p * v.x; acc.y += p * v.y; acc.z += p * v.z; acc.w += p * v.w;
    }
    float r = 1.f / sum;
    float4 bb = *(const float4*)(b1 + h * 128 + lane * 4);
    float4 o;
    o.x = acc.x * r + bb.x; o.y = acc.y * r + bb.y;
    o.z = acc.z * r + bb.z; o.w = acc.w * r + bb.w;
    o.x = o.x > 0.f ? o.x : 0.01f * o.x; o.y = o.y > 0.f ? o.y : 0.01f * o.y;
    o.z = o.z > 0.f ? o.z : 0.01f * o.z; o.w = o.w > 0.f ? o.w : 0.01f * o.w;
    size_t base = (size_t)n * 256 + h * 128 + lane * 4;
    split_store4(g_ahi + base, g_alo + base, o);
}

// ================= CSR gather layer 2: 2 warps per node (col halves) =================
__global__ __launch_bounds__(256) void gather_l2(const float* __restrict__ b2, int n0, int nCount) {
    int idx = blockIdx.x * blockDim.x + threadIdx.x;
    int nrel = idx >> 6;
    if (nrel >= nCount) return;
    int n = n0 + nrel;
    int h = (idx >> 5) & 1;
    int lane = idx & 31;
    float ad = __ldg(&g_ad2[n]);
    int beg = g_off[n], end = g_off[n + 1];
    float4 acc = make_float4(0.f, 0.f, 0.f, 0.f);
    float sum = 0.f;
    const float* hb = g_h2 + h * 128;
#pragma unroll 2
    for (int j = beg; j < end; j++) {
        int s = __ldg(&g_csr[j]);
        float e = __ldg(&g_as2[s]) + ad;
        e = e > 0.f ? e : 0.2f * e;
        float p = __expf(e);
        sum += p;
        float4 v = __ldg((const float4*)(hb + (size_t)s * 256) + lane);
        acc.x += p * v.x; acc.y += p * v.y; acc.z += p * v.z; acc.w += p * v.w;
    }
    {   // self loop
        float e = __ldg(&g_as2[n]) + ad;
        e = e > 0.f ? e : 0.2f * e;
        float p = __expf(e);
        sum += p;
        float4 v = __ldg((const float4*)(hb + (size_t)n * 256) + lane);
        acc.x += p * v.x; acc.y += p * v.y; acc.z += p * v.z; acc.w += p * v.w;
    }
    float r = 1.f / sum;
    float4 bb = *(const float4*)(b2 + h * 128 + lane * 4);
    float4 o;
    o.x = acc.x * r + bb.x; o.y = acc.y * r + bb.y;
    o.z = acc.z * r + bb.z; o.w = acc.w * r + bb.w;
    size_t base = (size_t)n * 256 + h * 128 + lane * 4;
    split_store4(g_ahi + base, g_alo + base, o);
}

// ================= launch =================
extern "C" void kernel_launch(void* const* d_in, const int* in_sizes, int n_in,
                              void* d_out, int out_size)
{
    const float* x      = (const float*)d_in[0];
    const int*   ei     = (const int*)d_in[1];      // int32 (JAX x64 disabled)
    const float* W1     = (const float*)d_in[2];
    const float* a_src1 = (const float*)d_in[3];
    const float* a_dst1 = (const float*)d_in[4];
    const float* b1     = (const float*)d_in[5];
    const float* W2     = (const float*)d_in[6];
    const float* a_src2 = (const float*)d_in[7];
    const float* a_dst2 = (const float*)d_in[8];
    const float* b2     = (const float*)d_in[9];
    const float* G      = (const float*)d_in[10];
    const float* mu     = (const float*)d_in[11];
    float* out = (float*)d_out;

    int N = in_sizes[0] / 256;
    int E = in_sizes[1] / 2;
    const int* src = ei;
    const int* dst = ei + E;

    static cudaStream_t sA = nullptr, sB = nullptr;
    static cudaEvent_t evFork = nullptr, evA = nullptr, evB = nullptr;
    static cudaEvent_t evM1 = nullptr, evG1a = nullptr, evG1b = nullptr;
    static cudaEvent_t evM2 = nullptr, evG2a = nullptr, evG2b = nullptr, evDone = nullptr;
    if (!sA) {
        cudaFuncSetAttribute(gemm_hmma, cudaFuncAttributeMaxDynamicSharedMemorySize, SMEM_B);
        cudaStreamCreateWithFlags(&sA, cudaStreamNonBlocking);
        cudaStreamCreateWithFlags(&sB, cudaStreamNonBlocking);
        cudaEventCreateWithFlags(&evFork, cudaEventDisableTiming);
        cudaEventCreateWithFlags(&evA, cudaEventDisableTiming);
        cudaEventCreateWithFlags(&evB, cudaEventDisableTiming);
        cudaEventCreateWithFlags(&evM1, cudaEventDisableTiming);
        cudaEventCreateWithFlags(&evG1a, cudaEventDisableTiming);
        cudaEventCreateWithFlags(&evG1b, cudaEventDisableTiming);
        cudaEventCreateWithFlags(&evM2, cudaEventDisableTiming);
        cudaEventCreateWithFlags(&evG2a, cudaEventDisableTiming);
        cudaEventCreateWithFlags(&evG2b, cudaEventDisableTiming);
        cudaEventCreateWithFlags(&evDone, cudaEventDisableTiming);
    }

    size_t nel = (size_t)N * 256;
    size_t n4 = nel / 4;
    int gemm_bx = (N + 127) / 128;
    int nb = (N + 1023) / 1024;

    // row chunking for gather->gemm overlap: H multiple of 128
    int H = ((N / 2 + 127) / 128) * 128;
    if (H >= N) H = (N > 128) ? N - 128 : N;
    int N1 = N - H;
    int gx0 = (H + 127) / 128;
    int gx1 = (N1 + 127) / 128;

    // ---- fork ----
    cudaEventRecord(evFork, 0);
    cudaStreamWaitEvent(sA, evFork, 0);
    cudaStreamWaitEvent(sB, evFork, 0);

    // ---- stream A: CSR build (+ alpha2 accumulator zero) ----
    zero_init<<<(N + 255) / 256, 256, 0, sA>>>(N);
    hist_kernel<<<(E + 255) / 256, 256, 0, sA>>>(dst, E);
    scan_blk<<<nb, 1024, 0, sA>>>(N);
    scan_top<<<1, 64, 0, sA>>>(nb);
    scan_add<<<(N + 255) / 256, 256, 0, sA>>>(N, E);
    scatter_kernel<<<(E + 255) / 256, 256, 0, sA>>>(src, dst, E);
    cudaEventRecord(evA, sA);

    // ---- stream B: all weight splits ----
    split_w<<<(256 * 256 + 255) / 256, 256, 0, sB>>>(W1, 0, 256 * 256);
    split_w<<<(256 * 256 + 255) / 256, 256, 0, sB>>>(W2, 1, 256 * 256);
    tsplit_g<<<dim3(32, 8), dim3(32, 8), 0, sB>>>(G);
    cudaEventRecord(evB, sB);

    // ---- main stream: split_x, gemm1 (full) ----
    split_x4<<<(int)((n4 + 255) / 256), 256>>>((const float4*)x, n4);
    cudaStreamWaitEvent(0, evB, 0);
    gemm_hmma<<<dim3(gemm_bx, 2), 256, SMEM_B>>>(N, 0, 0, a_src1, a_dst1, nullptr, nullptr);
    cudaEventRecord(evM1, 0);

    // ---- gather1 chunks on main stream (needs full h1 + CSR) ----
    cudaStreamWaitEvent(0, evA, 0);
    gather_l1<<<(H * 64 + 255) / 256, 256>>>(b1, 0, H);
    cudaEventRecord(evG1a, 0);
    if (N1 > 0) gather_l1<<<(N1 * 64 + 255) / 256, 256>>>(b1, H, N1);
    cudaEventRecord(evG1b, 0);

    // ---- gemm2 chunks on stream B, overlapped with gather1 chunk1 ----
    cudaStreamWaitEvent(sB, evG1a, 0);
    gemm_hmma<<<dim3(gx0, 2), 256, SMEM_B, sB>>>(N, 0, 1, a_src2, a_dst2, nullptr, nullptr);
    cudaStreamWaitEvent(sB, evG1b, 0);
    if (N1 > 0) gemm_hmma<<<dim3(gx1, 2), 256, SMEM_B, sB>>>(N, H, 1, a_src2, a_dst2, nullptr, nullptr);
    cudaEventRecord(evM2, sB);

    // ---- gather2 chunks on main stream (needs full h2 + alpha2) ----
    cudaStreamWaitEvent(0, evM2, 0);
    gather_l2<<<(H * 64 + 255) / 256, 256>>>(b2, 0, H);
    cudaEventRecord(evG2a, 0);
    if (N1 > 0) gather_l2<<<(N1 * 64 + 255) / 256, 256>>>(b2, H, N1);
    cudaEventRecord(evG2b, 0);

    // ---- gemm3 chunks on stream B, overlapped with gather2 chunk1 ----
    cudaStreamWaitEvent(sB, evG2a, 0);
    gemm_hmma<<<dim3(gx0, 8), 256, SMEM_B, sB>>>(N, 0, 2, nullptr, nullptr, mu, out);
    cudaStreamWaitEvent(sB, evG2b, 0);
    if (N1 > 0) gemm_hmma<<<dim3(gx1, 8), 256, SMEM_B, sB>>>(N, H, 2, nullptr, nullptr, mu, out);
    cudaEventRecord(evDone, sB);

    // ---- join ----
    cudaStreamWaitEvent(0, evDone, 0);
}

// round 17
// speedup vs baseline: 1.0474x; 1.0474x over previous
#include <cuda_runtime.h>
#include <cuda_bf16.h>
#include <cstdint>
#include <math.h>

#define NMAX 50000
#define EMAX 800000

// ================= scratch (device globals) =================
__device__ __align__(16) float g_h1[(size_t)NMAX * 256];
__device__ __align__(16) float g_h2[(size_t)NMAX * 256];
__device__ __align__(16) float g_as1[NMAX * 2];
__device__ __align__(16) float g_ad1[NMAX * 2];
__device__ __align__(16) float g_as2[NMAX];
__device__ __align__(16) float g_ad2[NMAX];
// CSR by destination
__device__ int g_deg[NMAX];
__device__ int g_off[NMAX + 1];
__device__ int g_cur[NMAX];
__device__ int g_csr[EMAX];
__device__ int g_blksum[64];
// split-bf16 operands
__device__ __align__(16) __nv_bfloat16 g_ahi[(size_t)NMAX * 256];
__device__ __align__(16) __nv_bfloat16 g_alo[(size_t)NMAX * 256];
__device__ __align__(16) __nv_bfloat16 g_bhi[256 * 256];      // W1
__device__ __align__(16) __nv_bfloat16 g_blo[256 * 256];
__device__ __align__(16) __nv_bfloat16 g_w2hi[256 * 256];     // W2
__device__ __align__(16) __nv_bfloat16 g_w2lo[256 * 256];
__device__ __align__(16) __nv_bfloat16 g_ghi[(size_t)1024 * 256];  // G^T
__device__ __align__(16) __nv_bfloat16 g_glo[(size_t)1024 * 256];

__device__ __forceinline__ uint32_t smem_u32(const void* p) {
    uint32_t a;
    asm("{ .reg .u64 t; cvta.to.shared.u64 t, %1; cvt.u32.u64 %0, t; }" : "=r"(a) : "l"(p));
    return a;
}

// ================= split store helper =================
__device__ __forceinline__ void split_store4(__nv_bfloat16* hip, __nv_bfloat16* lop, float4 v) {
    __nv_bfloat16 h0 = __float2bfloat16(v.x), h1 = __float2bfloat16(v.y);
    __nv_bfloat16 h2 = __float2bfloat16(v.z), h3 = __float2bfloat16(v.w);
    __nv_bfloat16 l0 = __float2bfloat16(v.x - __bfloat162float(h0));
    __nv_bfloat16 l1 = __float2bfloat16(v.y - __bfloat162float(h1));
    __nv_bfloat16 l2 = __float2bfloat16(v.z - __bfloat162float(h2));
    __nv_bfloat16 l3 = __float2bfloat16(v.w - __bfloat162float(h3));
    uint2 uh = make_uint2(((uint32_t)__bfloat16_as_ushort(h1) << 16) | __bfloat16_as_ushort(h0),
                          ((uint32_t)__bfloat16_as_ushort(h3) << 16) | __bfloat16_as_ushort(h2));
    uint2 ul = make_uint2(((uint32_t)__bfloat16_as_ushort(l1) << 16) | __bfloat16_as_ushort(l0),
                          ((uint32_t)__bfloat16_as_ushort(l3) << 16) | __bfloat16_as_ushort(l2));
    *(uint2*)hip = uh;
    *(uint2*)lop = ul;
}

// ================= CSR build (hierarchical scan) =================
__global__ void zero_init(int N) {
    int i = blockIdx.x * blockDim.x + threadIdx.x;
    if (i < N) {
        g_deg[i] = 0;
        g_as2[i] = 0.f;
        g_ad2[i] = 0.f;
    }
}
__global__ void hist_kernel(const int* __restrict__ dst, int E) {
    int e = blockIdx.x * blockDim.x + threadIdx.x;
    if (e < E) atomicAdd(&g_deg[dst[e]], 1);
}
__global__ void scan_blk(int N) {
    __shared__ int sh[1024];
    int b = blockIdx.x, tid = threadIdx.x;
    int i = b * 1024 + tid;
    int v = (i < N) ? g_deg[i] : 0;
    sh[tid] = v;
    __syncthreads();
    for (int o = 1; o < 1024; o <<= 1) {
        int t = (tid >= o) ? sh[tid - o] : 0;
        __syncthreads();
        sh[tid] += t;
        __syncthreads();
    }
    if (i < N) g_off[i] = sh[tid] - v;
    if (tid == 1023) g_blksum[b] = sh[1023];
}
__global__ void scan_top(int nb) {
    __shared__ int sh[64];
    int tid = threadIdx.x;
    int v = (tid < nb) ? g_blksum[tid] : 0;
    sh[tid] = v;
    __syncthreads();
    for (int o = 1; o < 64; o <<= 1) {
        int t = (tid >= o) ? sh[tid - o] : 0;
        __syncthreads();
        sh[tid] += t;
        __syncthreads();
    }
    if (tid < nb) g_blksum[tid] = sh[tid] - v;
}
__global__ void scan_add(int N, int E) {
    int i = blockIdx.x * blockDim.x + threadIdx.x;
    if (i < N) {
        int o = g_off[i] + g_blksum[i >> 10];
        g_off[i] = o;
        g_cur[i] = o;
    }
    if (i == 0) g_off[N] = E;
}
__global__ void scatter_kernel(const int* __restrict__ src, const int* __restrict__ dst, int E) {
    int e = blockIdx.x * blockDim.x + threadIdx.x;
    if (e >= E) return;
    int pos = atomicAdd(&g_cur[dst[e]], 1);
    g_csr[pos] = src[e];
}

// ================= split-bf16 conversions =================
__global__ void split_x4(const float4* __restrict__ x4, size_t n4) {
    size_t i = (size_t)blockIdx.x * blockDim.x + threadIdx.x;
    if (i >= n4) return;
    float4 v = __ldg(&x4[i]);
    split_store4(g_ahi + i * 4, g_alo + i * 4, v);
}
__global__ void split_w(const float* __restrict__ W, int sel, size_t n) {
    size_t i = (size_t)blockIdx.x * blockDim.x + threadIdx.x;
    if (i >= n) return;
    float v = W[i];
    __nv_bfloat16 h = __float2bfloat16(v);
    __nv_bfloat16 l = __float2bfloat16(v - __bfloat162float(h));
    if (sel == 0) { g_bhi[i] = h;  g_blo[i] = l; }
    else          { g_w2hi[i] = h; g_w2lo[i] = l; }
}
__global__ void tsplit_g(const float* __restrict__ G) {
    __shared__ float t[32][33];
    int bx = blockIdx.x, by = blockIdx.y;
    int x = threadIdx.x, y = threadIdx.y;   // 32 x 8
#pragma unroll
    for (int i = 0; i < 4; i++)
        t[y + i * 8][x] = G[(size_t)(by * 32 + y + i * 8) * 1024 + bx * 32 + x];
    __syncthreads();
#pragma unroll
    for (int i = 0; i < 4; i++) {
        float v = t[x][y + i * 8];
        size_t idx = (size_t)(bx * 32 + y + i * 8) * 256 + by * 32 + x;
        __nv_bfloat16 h = __float2bfloat16(v);
        g_ghi[idx] = h;
        g_glo[idx] = __float2bfloat16(v - __bfloat162float(h));
    }
}

// ================= HMMA (mma.sync) GEMM =================
#define TILE_B   10240          // 128 rows * 80B (32 bf16 + 8 pad)
#define STAGE_B  (4 * TILE_B)
#define SMEM_B   (2 * STAGE_B)  // 81920 B

__device__ __forceinline__ void ldsm_x4(uint32_t* r, uint32_t addr) {
    asm volatile("ldmatrix.sync.aligned.m8n8.x4.shared.b16 {%0,%1,%2,%3}, [%4];"
        : "=r"(r[0]), "=r"(r[1]), "=r"(r[2]), "=r"(r[3]) : "r"(addr));
}
__device__ __forceinline__ void mma_bf16(float* c, const uint32_t* a, const uint32_t* b) {
    asm volatile("mma.sync.aligned.m16n8k16.row.col.f32.bf16.bf16.f32 "
        "{%0,%1,%2,%3}, {%4,%5,%6,%7}, {%8,%9}, {%0,%1,%2,%3};"
        : "+f"(c[0]), "+f"(c[1]), "+f"(c[2]), "+f"(c[3])
        : "r"(a[0]), "r"(a[1]), "r"(a[2]), "r"(a[3]), "r"(b[0]), "r"(b[1]));
}
__device__ __forceinline__ void cp16(uint32_t saddr, const void* gaddr, int szbytes) {
    asm volatile("cp.async.cg.shared.global [%0], [%1], 16, %2;"
        :: "r"(saddr), "l"(gaddr), "r"(szbytes));
}
__device__ __forceinline__ void load_tile(char* st, const __nv_bfloat16* gsrc,
                                          int grow_base, int grow_limit, int k0, int tid)
{
#pragma unroll
    for (int j = 0; j < 2; j++) {
        int idx = tid * 2 + j;
        int row = idx >> 2, kc = idx & 3;
        int grow = grow_base + row;
        int ok = (grow < grow_limit);
        const __nv_bfloat16* gp = gsrc + (size_t)(ok ? grow : 0) * 256 + k0 + kc * 8;
        uint32_t sa = smem_u32(st + row * 80 + kc * 16);
        cp16(sa, gp, ok ? 16 : 0);
    }
}

__global__ __launch_bounds__(256, 2) void gemm_hmma(
    int Nrows, int mode, const float* __restrict__ av_s, const float* __restrict__ av_d,
    const float* __restrict__ mu, float* __restrict__ outp)
{
    extern __shared__ char smem[];
    int tid = threadIdx.x;
    int wid = tid >> 5;
    int lane = tid & 31;
    int warp_m = wid & 3;
    int warp_n = wid >> 2;
    int bm = blockIdx.x * 128;
    int bn = blockIdx.y * 128;

    const __nv_bfloat16* Bhi = (mode == 0) ? g_bhi : (mode == 1 ? g_w2hi : g_ghi);
    const __nv_bfloat16* Blo = (mode == 0) ? g_blo : (mode == 1 ? g_w2lo : g_glo);

    float acc[2][8][4];
#pragma unroll
    for (int mt = 0; mt < 2; mt++)
#pragma unroll
        for (int nt = 0; nt < 8; nt++)
#pragma unroll
            for (int j = 0; j < 4; j++) acc[mt][nt][j] = 0.f;

    {
        char* s0 = smem;
        load_tile(s0,              g_ahi, bm, Nrows, 0, tid);
        load_tile(s0 + TILE_B,     g_alo, bm, Nrows, 0, tid);
        load_tile(s0 + 2 * TILE_B, Bhi, bn, 1 << 30, 0, tid);
        load_tile(s0 + 3 * TILE_B, Blo, bn, 1 << 30, 0, tid);
        asm volatile("cp.async.commit_group;" ::: "memory");
    }

    for (int c = 0; c < 8; c++) {
        if (c < 7) {
            char* sn = smem + ((c + 1) & 1) * STAGE_B;
            int k0 = (c + 1) * 32;
            load_tile(sn,              g_ahi, bm, Nrows, k0, tid);
            load_tile(sn + TILE_B,     g_alo, bm, Nrows, k0, tid);
            load_tile(sn + 2 * TILE_B, Bhi, bn, 1 << 30, k0, tid);
            load_tile(sn + 3 * TILE_B, Blo, bn, 1 << 30, k0, tid);
            asm volatile("cp.async.commit_group;" ::: "memory");
            asm volatile("cp.async.wait_group 1;" ::: "memory");
        } else {
            asm volatile("cp.async.wait_group 0;" ::: "memory");
        }
        __syncthreads();

        char* sa_hi = smem + (c & 1) * STAGE_B;
        char* sa_lo = sa_hi + TILE_B;
        char* sb_hi = sa_hi + 2 * TILE_B;
        char* sb_lo = sa_hi + 3 * TILE_B;

#pragma unroll
        for (int ks = 0; ks < 2; ks++) {
            uint32_t ah[2][4], al[2][4];
#pragma unroll
            for (int mt = 0; mt < 2; mt++) {
                int row = warp_m * 32 + mt * 16 + (lane & 7) + ((lane >> 3) & 1) * 8;
                int kc = ks * 2 + (lane >> 4);
                uint32_t off = (uint32_t)(row * 80 + kc * 16);
                ldsm_x4(ah[mt], smem_u32(sa_hi + off));
                ldsm_x4(al[mt], smem_u32(sa_lo + off));
            }
            int g = lane >> 3;
#pragma unroll
            for (int np = 0; np < 4; np++) {
                int n0 = np * 2, n1 = np * 2 + 1;
                int brow = warp_n * 64 + (n0 + (g >> 1)) * 8 + (lane & 7);
                int bkc = ks * 2 + (g & 1);
                uint32_t boff = (uint32_t)(brow * 80 + bkc * 16);
                uint32_t bh[4], bl[4];
                ldsm_x4(bh, smem_u32(sb_hi + boff));
                ldsm_x4(bl, smem_u32(sb_lo + boff));
                mma_bf16(acc[0][n0], ah[0], bh);
                mma_bf16(acc[1][n0], ah[1], bh);
                mma_bf16(acc[0][n1], ah[0], bh + 2);
                mma_bf16(acc[1][n1], ah[1], bh + 2);
                mma_bf16(acc[0][n0], ah[0], bl);
                mma_bf16(acc[1][n0], ah[1], bl);
                mma_bf16(acc[0][n1], ah[0], bl + 2);
                mma_bf16(acc[1][n1], ah[1], bl + 2);
                mma_bf16(acc[0][n0], al[0], bh);
                mma_bf16(acc[1][n0], al[1], bh);
                mma_bf16(acc[0][n1], al[0], bh + 2);
                mma_bf16(acc[1][n1], al[1], bh + 2);
            }
        }
        __syncthreads();
    }

    // ================= epilogue =================
    if (mode < 2) {
        float* C = (mode == 0) ? g_h1 : g_h2;
#pragma unroll
        for (int mt = 0; mt < 2; mt++) {
            int r0 = bm + warp_m * 32 + mt * 16 + (lane >> 2);
#pragma unroll
            for (int nt = 0; nt < 8; nt++) {
                int gcol = bn + warp_n * 64 + nt * 8 + (lane & 3) * 2;
                if (r0 < Nrows)
                    *(float2*)(C + (size_t)r0 * 256 + gcol) =
                        make_float2(acc[mt][nt][0], acc[mt][nt][1]);
                if (r0 + 8 < Nrows)
                    *(float2*)(C + (size_t)(r0 + 8) * 256 + gcol) =
                        make_float2(acc[mt][nt][2], acc[mt][nt][3]);
            }
        }
        const float* asv = av_s + bn;
        const float* adv = av_d + bn;
        float psrc[2][2] = {{0.f, 0.f}, {0.f, 0.f}};
        float pdst[2][2] = {{0.f, 0.f}, {0.f, 0.f}};
#pragma unroll
        for (int nt = 0; nt < 8; nt++) {
            int col = warp_n * 64 + nt * 8 + (lane & 3) * 2;
            float s0 = __ldg(&asv[col]), s1 = __ldg(&asv[col + 1]);
            float d0 = __ldg(&adv[col]), d1 = __ldg(&adv[col + 1]);
#pragma unroll
            for (int mt = 0; mt < 2; mt++) {
                psrc[mt][0] += acc[mt][nt][0] * s0 + acc[mt][nt][1] * s1;
                psrc[mt][1] += acc[mt][nt][2] * s0 + acc[mt][nt][3] * s1;
                pdst[mt][0] += acc[mt][nt][0] * d0 + acc[mt][nt][1] * d1;
                pdst[mt][1] += acc[mt][nt][2] * d0 + acc[mt][nt][3] * d1;
            }
        }
#pragma unroll
        for (int o = 1; o <= 2; o <<= 1) {
#pragma unroll
            for (int mt = 0; mt < 2; mt++)
#pragma unroll
                for (int h = 0; h < 2; h++) {
                    psrc[mt][h] += __shfl_xor_sync(0xffffffffu, psrc[mt][h], o);
                    pdst[mt][h] += __shfl_xor_sync(0xffffffffu, pdst[mt][h], o);
                }
        }
        float* sred = (float*)smem;
        if ((lane & 3) == 0) {
#pragma unroll
            for (int mt = 0; mt < 2; mt++)
#pragma unroll
                for (int h = 0; h < 2; h++) {
                    int rl = warp_m * 32 + mt * 16 + h * 8 + (lane >> 2);
                    sred[warp_n * 256 + rl] = psrc[mt][h];
                    sred[warp_n * 256 + 128 + rl] = pdst[mt][h];
                }
        }
        __syncthreads();
        if (tid < 128 && bm + tid < Nrows) {
            float vs = sred[tid] + sred[256 + tid];
            float vd = sred[128 + tid] + sred[384 + tid];
            int row = bm + tid;
            if (mode == 0) {
                g_as1[row * 2 + blockIdx.y] = vs;
                g_ad1[row * 2 + blockIdx.y] = vd;
            } else {
                atomicAdd(&g_as2[row], vs);
                atomicAdd(&g_ad2[row], vd);
            }
        }
    } else {
        int kb = blockIdx.y;
        const float* muk = mu + kb * 128;
        float pn[2][2], psq[2][2];
#pragma unroll
        for (int mt = 0; mt < 2; mt++)
#pragma unroll
            for (int h = 0; h < 2; h++) { pn[mt][h] = 0.f; psq[mt][h] = 0.f; }
#pragma unroll
        for (int nt = 0; nt < 8; nt++) {
            int col = warp_n * 64 + nt * 8 + (lane & 3) * 2;
            float m0 = __ldg(&muk[col]), m1 = __ldg(&muk[col + 1]);
#pragma unroll
            for (int mt = 0; mt < 2; mt++) {
                float c0 = acc[mt][nt][0], c1 = acc[mt][nt][1];
                float c2 = acc[mt][nt][2], c3 = acc[mt][nt][3];
                pn[mt][0] += c0 * m0 + c1 * m1;  psq[mt][0] += c0 * c0 + c1 * c1;
                pn[mt][1] += c2 * m0 + c3 * m1;  psq[mt][1] += c2 * c2 + c3 * c3;
            }
        }
#pragma unroll
        for (int o = 1; o <= 2; o <<= 1) {
#pragma unroll
            for (int mt = 0; mt < 2; mt++)
#pragma unroll
                for (int h = 0; h < 2; h++) {
                    pn[mt][h]  += __shfl_xor_sync(0xffffffffu, pn[mt][h], o);
                    psq[mt][h] += __shfl_xor_sync(0xffffffffu, psq[mt][h], o);
                }
        }
        float2* sred = (float2*)smem;
        if ((lane & 3) == 0) {
#pragma unroll
            for (int mt = 0; mt < 2; mt++)
#pragma unroll
                for (int h = 0; h < 2; h++) {
                    int rl = warp_m * 32 + mt * 16 + h * 8 + (lane >> 2);
                    sred[warp_n * 128 + rl] = make_float2(pn[mt][h], psq[mt][h]);
                }
        }
        __syncthreads();
        if (tid < 128) {
            float2 p0 = sred[tid], p1 = sred[128 + tid];
            float num = p0.x + p1.x;
            float sq  = p0.y + p1.y;
            float musq = 0.f;
#pragma unroll 16
            for (int j = 0; j < 128; j++) {
                float mv = __ldg(&muk[j]);
                musq += mv * mv;
            }
            int m = bm + tid;
            if (m < Nrows)
                outp[(size_t)m * 8 + kb] = num / fmaxf(sqrtf(sq) * sqrtf(musq), 1e-8f);
        }
    }
}

// ================= CSR gather layer 1: 2 warps per node (warp = head) =================
__global__ __launch_bounds__(256) void gather_l1(const float* __restrict__ b1, int N) {
    int idx = blockIdx.x * blockDim.x + threadIdx.x;
    int n = idx >> 6;
    if (n >= N) return;
    int h = (idx >> 5) & 1;
    int lane = idx & 31;
    float ad = __ldg(&g_ad1[2 * n + h]);
    int beg = g_off[n], end = g_off[n + 1];
    float4 acc = make_float4(0.f, 0.f, 0.f, 0.f);
    float sum = 0.f;
    const float* hb = g_h1 + h * 128;
#pragma unroll 2
    for (int j = beg; j < end; j++) {
        int s = __ldg(&g_csr[j]);
        float e = __ldg(&g_as1[2 * s + h]) + ad;
        e = e > 0.f ? e : 0.2f * e;
        float p = __expf(e);
        sum += p;
        float4 v = __ldg((const float4*)(hb + (size_t)s * 256) + lane);
        acc.x += p * v.x; acc.y += p * v.y; acc.z += p * v.z; acc.w += p * v.w;
    }
    {   // self loop
        float e = __ldg(&g_as1[2 * n + h]) + ad;
        e = e > 0.f ? e : 0.2f * e;
        float p = __expf(e);
        sum += p;
        float4 v = __ldg((const float4*)(hb + (size_t)n * 256) + lane);
        acc.x += p * v.x; acc.y += p * v.y; acc.z += p * v.z; acc.w += p * v.w;
    }
    float r = 1.f / sum;
    float4 bb = *(const float4*)(b1 + h * 128 + lane * 4);
    float4 o;
    o.x = acc.x * r + bb.x; o.y = acc.y * r + bb.y;
    o.z = acc.z * r + bb.z; o.w = acc.w * r + bb.w;
    o.x = o.x > 0.f ? o.x : 0.01f * o.x; o.y = o.y > 0.f ? o.y : 0.01f * o.y;
    o.z = o.z > 0.f ? o.z : 0.01f * o.z; o.w = o.w > 0.f ? o.w : 0.01f * o.w;
    size_t base = (size_t)n * 256 + h * 128 + lane * 4;
    split_store4(g_ahi + base, g_alo + base, o);
}

// ================= CSR gather layer 2: 2 warps per node (col halves) =================
__global__ __launch_bounds__(256) void gather_l2(const float* __restrict__ b2, int N) {
    int idx = blockIdx.x * blockDim.x + threadIdx.x;
    int n = idx >> 6;
    if (n >= N) return;
    int h = (idx >> 5) & 1;
    int lane = idx & 31;
    float ad = __ldg(&g_ad2[n]);
    int beg = g_off[n], end = g_off[n + 1];
    float4 acc = make_float4(0.f, 0.f, 0.f, 0.f);
    float sum = 0.f;
    const float* hb = g_h2 + h * 128;
#pragma unroll 2
    for (int j = beg; j < end; j++) {
        int s = __ldg(&g_csr[j]);
        float e = __ldg(&g_as2[s]) + ad;
        e = e > 0.f ? e : 0.2f * e;
        float p = __expf(e);
        sum += p;
        float4 v = __ldg((const float4*)(hb + (size_t)s * 256) + lane);
        acc.x += p * v.x; acc.y += p * v.y; acc.z += p * v.z; acc.w += p * v.w;
    }
    {   // self loop
        float e = __ldg(&g_as2[n]) + ad;
        e = e > 0.f ? e : 0.2f * e;
        float p = __expf(e);
        sum += p;
        float4 v = __ldg((const float4*)(hb + (size_t)n * 256) + lane);
        acc.x += p * v.x; acc.y += p * v.y; acc.z += p * v.z; acc.w += p * v.w;
    }
    float r = 1.f / sum;
    float4 bb = *(const float4*)(b2 + h * 128 + lane * 4);
    float4 o;
    o.x = acc.x * r + bb.x; o.y = acc.y * r + bb.y;
    o.z = acc.z * r + bb.z; o.w = acc.w * r + bb.w;
    size_t base = (size_t)n * 256 + h * 128 + lane * 4;
    split_store4(g_ahi + base, g_alo + base, o);
}

// ================= launch (R15 schedule + W1-only gate for gemm1) =================
extern "C" void kernel_launch(void* const* d_in, const int* in_sizes, int n_in,
                              void* d_out, int out_size)
{
    const float* x      = (const float*)d_in[0];
    const int*   ei     = (const int*)d_in[1];      // int32 (JAX x64 disabled)
    const float* W1     = (const float*)d_in[2];
    const float* a_src1 = (const float*)d_in[3];
    const float* a_dst1 = (const float*)d_in[4];
    const float* b1     = (const float*)d_in[5];
    const float* W2     = (const float*)d_in[6];
    const float* a_src2 = (const float*)d_in[7];
    const float* a_dst2 = (const float*)d_in[8];
    const float* b2     = (const float*)d_in[9];
    const float* G      = (const float*)d_in[10];
    const float* mu     = (const float*)d_in[11];
    float* out = (float*)d_out;

    int N = in_sizes[0] / 256;
    int E = in_sizes[1] / 2;
    const int* src = ei;
    const int* dst = ei + E;

    static cudaStream_t sA = nullptr, sB = nullptr;
    static cudaEvent_t evFork = nullptr, evA = nullptr, evB = nullptr, evB1 = nullptr;
    if (!sA) {
        cudaFuncSetAttribute(gemm_hmma, cudaFuncAttributeMaxDynamicSharedMemorySize, SMEM_B);
        cudaStreamCreateWithFlags(&sA, cudaStreamNonBlocking);
        cudaStreamCreateWithFlags(&sB, cudaStreamNonBlocking);
        cudaEventCreateWithFlags(&evFork, cudaEventDisableTiming);
        cudaEventCreateWithFlags(&evA, cudaEventDisableTiming);
        cudaEventCreateWithFlags(&evB, cudaEventDisableTiming);
        cudaEventCreateWithFlags(&evB1, cudaEventDisableTiming);
    }

    size_t nel = (size_t)N * 256;
    size_t n4 = nel / 4;
    int gemm_bx = (N + 127) / 128;
    int gather_blocks = (N * 64 + 255) / 256;
    int nb = (N + 1023) / 1024;

    // ---- fork ----
    cudaEventRecord(evFork, 0);
    cudaStreamWaitEvent(sA, evFork, 0);
    cudaStreamWaitEvent(sB, evFork, 0);

    // ---- stream A: CSR build (+ alpha2 accumulator zero) ----
    zero_init<<<(N + 255) / 256, 256, 0, sA>>>(N);
    hist_kernel<<<(E + 255) / 256, 256, 0, sA>>>(dst, E);
    scan_blk<<<nb, 1024, 0, sA>>>(N);
    scan_top<<<1, 64, 0, sA>>>(nb);
    scan_add<<<(N + 255) / 256, 256, 0, sA>>>(N, E);
    scatter_kernel<<<(E + 255) / 256, 256, 0, sA>>>(src, dst, E);
    cudaEventRecord(evA, sA);

    // ---- stream B: weight splits; W1 gate first ----
    split_w<<<(256 * 256 + 255) / 256, 256, 0, sB>>>(W1, 0, 256 * 256);
    cudaEventRecord(evB1, sB);                       // W1 ready (gemm1 gate)
    split_w<<<(256 * 256 + 255) / 256, 256, 0, sB>>>(W2, 1, 256 * 256);
    tsplit_g<<<dim3(32, 8), dim3(32, 8), 0, sB>>>(G);
    cudaEventRecord(evB, sB);                        // all weights ready

    // ---- main stream: GEMM chain ----
    split_x4<<<(int)((n4 + 255) / 256), 256>>>((const float4*)x, n4);
    cudaStreamWaitEvent(0, evB1, 0);
    gemm_hmma<<<dim3(gemm_bx, 2), 256, SMEM_B>>>(N, 0, a_src1, a_dst1, nullptr, nullptr);
    cudaStreamWaitEvent(0, evA, 0);
    gather_l1<<<gather_blocks, 256>>>(b1, N);
    cudaStreamWaitEvent(0, evB, 0);                  // W2 + G ready (free: sB idle by now)
    gemm_hmma<<<dim3(gemm_bx, 2), 256, SMEM_B>>>(N, 1, a_src2, a_dst2, nullptr, nullptr);
    gather_l2<<<gather_blocks, 256>>>(b2, N);
    gemm_hmma<<<dim3(gemm_bx, 8), 256, SMEM_B>>>(N, 2, nullptr, nullptr, mu, out);
}